// round 7
// baseline (speedup 1.0000x reference)
#include <cuda_runtime.h>
#include <math.h>

#define NN 50000
#define NE 800000
#define IND 128

// ---------------- scratch ------------------------------------------------------
__device__ float g_hA[NN * 64];        // layer input (embed out / post-BN)
__device__ float g_hB[NN * 64];        // layer1 lin output (pre-BN)
__device__ float g_p[NN * 64];         // post-GEMM output (pre-lin)
__device__ float g_Hd[NN * 128];       // h @ preW_top  (dst half)
__device__ float g_Hs[NN * 128];       // h @ preW_bot  (src half) — 25.6MB, L2-resident
__device__ float g_agg[NN * 512];      // per node: [t][stat(mean,min,max,std)][f]
__device__ int   g_deg[NN];
__device__ float g_invc[NN];
__device__ float g_s1[NN];
__device__ float g_s2[NN];
__device__ int   g_rowptr[NN + 1];
__device__ int   g_cursor[NN];
__device__ int   g_csrc[NE];
__device__ float g_preB2[64 * 256];    // packed [k][c]: c<128 -> top(dst) half, c>=128 -> bottom(src)
__device__ float g_sumlog;
__device__ float g_bnsum[64];
__device__ float g_bnsq[64];
__device__ float g_bnscale[64];
__device__ float g_bnshift[64];

// ---------------- setup --------------------------------------------------------
__global__ void k_init() {
    int i = blockIdx.x * blockDim.x + threadIdx.x;
    if (i < NN) { g_deg[i] = 0; g_cursor[i] = 0; }
    if (i == 0) g_sumlog = 0.f;
    if (i < 64) { g_bnsum[i] = 0.f; g_bnsq[i] = 0.f; }
}

__global__ void k_degree(const int* __restrict__ dst) {
    int e = blockIdx.x * blockDim.x + threadIdx.x;
    if (e < NE) atomicAdd(&g_deg[dst[e]], 1);
}

__global__ void k_logsum() {
    __shared__ float s[256];
    int i = blockIdx.x * 256 + threadIdx.x;
    float v = 0.f;
    if (i < NN) v = logf((float)g_deg[i] + 1.f);
    s[threadIdx.x] = v; __syncthreads();
    for (int o = 128; o > 0; o >>= 1) {
        if (threadIdx.x < o) s[threadIdx.x] += s[threadIdx.x + o];
        __syncthreads();
    }
    if (threadIdx.x == 0) atomicAdd(&g_sumlog, s[0]);
}

__global__ void k_scales() {
    int i = blockIdx.x * blockDim.x + threadIdx.x;
    if (i >= NN) return;
    float avg = g_sumlog / (float)NN;
    float dc  = fmaxf((float)g_deg[i], 1.f);
    g_invc[i] = 1.f / dc;
    float ld  = logf(dc + 1.f);
    g_s1[i] = ld / avg;
    g_s2[i] = avg / ld;
}

__global__ void k_scan() {
    __shared__ int ssum[1024];
    const int CH = (NN + 1023) / 1024;
    int t  = threadIdx.x;
    int lo = t * CH, hi = min(lo + CH, NN);
    int s = 0;
    for (int i = lo; i < hi; i++) s += g_deg[i];
    ssum[t] = s; __syncthreads();
    for (int o = 1; o < 1024; o <<= 1) {
        int v = (t >= o) ? ssum[t - o] : 0;
        __syncthreads();
        ssum[t] += v;
        __syncthreads();
    }
    int run = (t == 0) ? 0 : ssum[t - 1];
    for (int i = lo; i < hi; i++) { g_rowptr[i] = run; run += g_deg[i]; }
    if (t == 1023) g_rowptr[NN] = ssum[1023];
}

__global__ void k_scatter(const int* __restrict__ src, const int* __restrict__ dst) {
    int e = blockIdx.x * blockDim.x + threadIdx.x;
    if (e >= NE) return;
    int d = dst[e];
    int pos = g_rowptr[d] + atomicAdd(&g_cursor[d], 1);
    g_csrc[pos] = src[e];
}

// pack preW (T,128,64) into B[64][256]: col c: half=c>>7, j=c&127, t=j>>6, f=j&63
__global__ void k_preB2(const float* __restrict__ preW) {
    int i = blockIdx.x * blockDim.x + threadIdx.x;
    if (i >= 64 * 256) return;
    int k = i >> 8, c = i & 255;
    int half = c >> 7, j = c & 127;
    int t = j >> 6, f = j & 63;
    g_preB2[i] = preW[t * 8192 + (half * 64 + k) * 64 + f];
}

// ---------------- embed GEMM: h = x @ W + b  (K=128, N=64) ----------------------
__global__ __launch_bounds__(256) void k_embed(const float* __restrict__ x,
                                               const float* __restrict__ W,
                                               const float* __restrict__ b) {
    __shared__ float Xs[128][64];
    __shared__ float Ws[128][64];
    int t  = threadIdx.x;
    int n0 = blockIdx.x * 64;

    for (int i = t; i < 2048; i += 256)
        ((float4*)Ws)[i] = ((const float4*)W)[i];

    int row = t & 63, kq = t >> 6;
    int gr = n0 + row;
#pragma unroll
    for (int j = 0; j < 8; j++) {
        int k = kq * 32 + j * 4;
        float4 v = make_float4(0.f, 0.f, 0.f, 0.f);
        if (gr < NN) v = *(const float4*)(x + (size_t)gr * IND + k);
        Xs[k][row] = v.x; Xs[k + 1][row] = v.y; Xs[k + 2][row] = v.z; Xs[k + 3][row] = v.w;
    }
    __syncthreads();

    int tx = t & 15, ty = t >> 4;
    float acc[4][4];
#pragma unroll
    for (int i = 0; i < 4; i++)
#pragma unroll
        for (int j = 0; j < 4; j++) acc[i][j] = 0.f;

#pragma unroll 8
    for (int k = 0; k < 128; k++) {
        float4 a  = *(const float4*)&Xs[k][ty * 4];
        float4 b4 = *(const float4*)&Ws[k][tx * 4];
        float ar[4] = {a.x, a.y, a.z, a.w};
        float br[4] = {b4.x, b4.y, b4.z, b4.w};
#pragma unroll
        for (int i = 0; i < 4; i++)
#pragma unroll
            for (int j = 0; j < 4; j++) acc[i][j] = fmaf(ar[i], br[j], acc[i][j]);
    }

    float4 bias = *(const float4*)(b + tx * 4);
#pragma unroll
    for (int i = 0; i < 4; i++) {
        int gn = n0 + ty * 4 + i;
        if (gn < NN) {
            float4 o = make_float4(acc[i][0] + bias.x, acc[i][1] + bias.y,
                                   acc[i][2] + bias.z, acc[i][3] + bias.w);
            *(float4*)(g_hA + (size_t)gn * 64 + tx * 4) = o;
        }
    }
}

// ---------------- Hd/Hs GEMM: [Hd|Hs] = h @ preB2  (K=64, N=256) ----------------
__global__ __launch_bounds__(256) void k_hds() {
    __shared__ float Xs[64][64];   // [k][node]
    __shared__ float Bs[64][64];   // [k][c]
    int t  = threadIdx.x;
    int n0 = blockIdx.x * 64;
    int cg = blockIdx.y * 64;

#pragma unroll
    for (int i = 0; i < 4; i++) {
        int u = t + 256 * i;
        int k = u >> 4, cq = u & 15;
        *(float4*)&Bs[k][cq * 4] = *(const float4*)(g_preB2 + k * 256 + cg + cq * 4);
    }
    int node = t & 63, kq = t >> 6;
    int gr = n0 + node;
#pragma unroll
    for (int j = 0; j < 4; j++) {
        int k = kq * 16 + j * 4;
        float4 v = make_float4(0.f, 0.f, 0.f, 0.f);
        if (gr < NN) v = *(const float4*)(g_hA + (size_t)gr * 64 + k);
        Xs[k][node] = v.x; Xs[k + 1][node] = v.y; Xs[k + 2][node] = v.z; Xs[k + 3][node] = v.w;
    }
    __syncthreads();

    int tx = t & 15, ty = t >> 4;
    float acc[4][4];
#pragma unroll
    for (int i = 0; i < 4; i++)
#pragma unroll
        for (int j = 0; j < 4; j++) acc[i][j] = 0.f;

#pragma unroll 8
    for (int k = 0; k < 64; k++) {
        float4 a  = *(const float4*)&Xs[k][ty * 4];
        float4 b4 = *(const float4*)&Bs[k][tx * 4];
        float ar[4] = {a.x, a.y, a.z, a.w};
        float br[4] = {b4.x, b4.y, b4.z, b4.w};
#pragma unroll
        for (int i = 0; i < 4; i++)
#pragma unroll
            for (int j = 0; j < 4; j++) acc[i][j] = fmaf(ar[i], br[j], acc[i][j]);
    }

    int c0 = cg + tx * 4;
#pragma unroll
    for (int i = 0; i < 4; i++) {
        int gn = n0 + ty * 4 + i;
        if (gn < NN) {
            float4 o = make_float4(acc[i][0], acc[i][1], acc[i][2], acc[i][3]);
            if (c0 < 128) *(float4*)(g_Hd + (size_t)gn * 128 + c0) = o;
            else          *(float4*)(g_Hs + (size_t)gn * 128 + (c0 - 128)) = o;
        }
    }
}

// ---------------- fused gather+aggregate (no edge-message materialization) ------
// m[e] = c_n + s_e  where c_n = Hd[n]+preb (const per node), s_e = Hs[src[e]].
// mean(m)=c+mean(s); min(m)=c+min(s); max(m)=c+max(s); std(m)=std(s).
__global__ void k_agg(const float* __restrict__ preb) {
    int n = blockIdx.x;
    int f = threadIdx.x;           // 0..127
    int lo = g_rowptr[n], hi = g_rowptr[n + 1];
    float sum = 0.f, sq = 0.f;
    float mn = INFINITY, mx = -INFINITY;
    int p = lo;
    for (; p + 4 <= hi; p += 4) {
        int i0 = g_csrc[p], i1 = g_csrc[p + 1], i2 = g_csrc[p + 2], i3 = g_csrc[p + 3];
        float v0 = g_Hs[(size_t)i0 * 128 + f];
        float v1 = g_Hs[(size_t)i1 * 128 + f];
        float v2 = g_Hs[(size_t)i2 * 128 + f];
        float v3 = g_Hs[(size_t)i3 * 128 + f];
        sum += (v0 + v1) + (v2 + v3);
        sq  = fmaf(v0, v0, fmaf(v1, v1, fmaf(v2, v2, fmaf(v3, v3, sq))));
        mn = fminf(mn, fminf(fminf(v0, v1), fminf(v2, v3)));
        mx = fmaxf(mx, fmaxf(fmaxf(v0, v1), fmaxf(v2, v3)));
    }
    for (; p < hi; p++) {
        float v = g_Hs[(size_t)g_csrc[p] * 128 + f];
        sum += v; sq = fmaf(v, v, sq);
        mn = fminf(mn, v); mx = fmaxf(mx, v);
    }
    float c = g_Hd[(size_t)n * 128 + f] + preb[f];
    int deg = hi - lo;
    float mean, mnO, mxO, sd;
    if (deg > 0) {
        float invc = g_invc[n];
        float ms  = sum * invc;
        float var = sq * invc - ms * ms;
        mean = c + ms; mnO = c + mn; mxO = c + mx;
        sd = sqrtf(fmaxf(var, 0.f) + 1e-5f);
    } else {
        mean = 0.f; mnO = 0.f; mxO = 0.f; sd = sqrtf(1e-5f);
    }
    int tt = f >> 6, ff = f & 63;
    size_t base = (size_t)n * 512 + tt * 256 + ff;
    g_agg[base]       = mean;
    g_agg[base + 64]  = mnO;
    g_agg[base + 128] = mxO;
    g_agg[base + 192] = sd;
}

// ---------------- post GEMM: 64 nodes x 64 cols, 128 threads, 4x8/thread --------
// K = 832 per tower (h 64 | agg 256 | agg*s1 256 | agg*s2 256), 13 chunks of 64.
// 48B smem per 32 FMA per kk (0.67 FMA/B) -> fma-bound, not smem-BW-bound.
__global__ __launch_bounds__(128) void k_post(const float* __restrict__ postW,
                                              const float* __restrict__ postb) {
    __shared__ float A13[2][64][68];   // [tower][node][k]  — 34816 B
    __shared__ float Ws[64][64];       // [kk][c], c = t*32+g — 16384 B
    int t  = threadIdx.x;              // 0..127
    int n0 = blockIdx.x * 64;
    int tx = t & 7, ty = t >> 3;       // tx: col-oct (8 cols), ty: node-quad (0..15)
    int tc = tx >> 2;                  // tower for this thread's columns

    float acc[4][8];
#pragma unroll
    for (int i = 0; i < 4; i++)
#pragma unroll
        for (int j = 0; j < 8; j++) acc[i][j] = 0.f;

    for (int ci = 0; ci < 13; ci++) {
        int kc = ci * 64;
        __syncthreads();   // previous kk-loop fully consumed smem
        // fill A13: 2048 float4 / 128 threads = 16 each
#pragma unroll
        for (int i = 0; i < 16; i++) {
            int u = t + 128 * i;
            int tw = u >> 10, node = (u >> 4) & 63, kq = u & 15;
            int gn = n0 + node;
            float4 v = make_float4(0.f, 0.f, 0.f, 0.f);
            if (gn < NN) {
                if (ci == 0) {
                    v = *(const float4*)(g_hA + (size_t)gn * 64 + kq * 4);
                } else {
                    int k = kc + kq * 4;
                    int j; float s = 1.f;
                    if (ci < 5)      { j = k - 64; }
                    else if (ci < 9) { j = k - 320; s = g_s1[gn]; }
                    else             { j = k - 576; s = g_s2[gn]; }
                    v = *(const float4*)(g_agg + (size_t)gn * 512 + tw * 256 + j);
                    v.x *= s; v.y *= s; v.z *= s; v.w *= s;
                }
            }
            *(float4*)&A13[tw][node][kq * 4] = v;
        }
        // fill Ws: 1024 float4 / 128 threads = 8 each
#pragma unroll
        for (int i = 0; i < 8; i++) {
            int u = t + 128 * i;
            int kk = u >> 4, cq = u & 15;
            int tw = cq >> 3, g = (cq * 4) & 31;
            ((float4*)Ws)[u] = *(const float4*)(postW + tw * 26624 + (kc + kk) * 32 + g);
        }
        __syncthreads();

#pragma unroll 8
        for (int kk = 0; kk < 64; kk++) {
            float ar[4];
#pragma unroll
            for (int i = 0; i < 4; i++) ar[i] = A13[tc][ty * 4 + i][kk];
            float4 b0 = *(const float4*)&Ws[kk][tx * 8];
            float4 b1 = *(const float4*)&Ws[kk][tx * 8 + 4];
            float br[8] = {b0.x, b0.y, b0.z, b0.w, b1.x, b1.y, b1.z, b1.w};
#pragma unroll
            for (int i = 0; i < 4; i++)
#pragma unroll
                for (int j = 0; j < 8; j++) acc[i][j] = fmaf(ar[i], br[j], acc[i][j]);
        }
    }

    float4 pb0 = *(const float4*)(postb + tx * 8);
    float4 pb1 = *(const float4*)(postb + tx * 8 + 4);
#pragma unroll
    for (int i = 0; i < 4; i++) {
        int gn = n0 + ty * 4 + i;
        if (gn < NN) {
            float4 o0 = make_float4(acc[i][0] + pb0.x, acc[i][1] + pb0.y,
                                    acc[i][2] + pb0.z, acc[i][3] + pb0.w);
            float4 o1 = make_float4(acc[i][4] + pb1.x, acc[i][5] + pb1.y,
                                    acc[i][6] + pb1.z, acc[i][7] + pb1.w);
            *(float4*)(g_p + (size_t)gn * 64 + tx * 8)     = o0;
            *(float4*)(g_p + (size_t)gn * 64 + tx * 8 + 4) = o1;
        }
    }
}

// ---------------- lin GEMM: out = P @ linW + linb (K=64) ------------------------
__global__ __launch_bounds__(256) void k_lin(const float* __restrict__ W,
                                             const float* __restrict__ b,
                                             float* __restrict__ outp) {
    __shared__ float Ps[64][68];
    __shared__ float Ws[64][64];
    int t  = threadIdx.x;
    int n0 = blockIdx.x * 64;

    for (int i = t; i < 1024; i += 256) ((float4*)Ws)[i] = ((const float4*)W)[i];
#pragma unroll
    for (int i = 0; i < 4; i++) {
        int u = t + 256 * i;
        int node = u >> 4, kq = u & 15;
        int gn = n0 + node;
        float4 v = make_float4(0.f, 0.f, 0.f, 0.f);
        if (gn < NN) v = *(const float4*)(g_p + (size_t)gn * 64 + kq * 4);
        *(float4*)&Ps[node][kq * 4] = v;
    }
    __syncthreads();

    int tx = t & 15, ty = t >> 4;
    float acc[4][4];
#pragma unroll
    for (int i = 0; i < 4; i++)
#pragma unroll
        for (int j = 0; j < 4; j++) acc[i][j] = 0.f;

#pragma unroll 8
    for (int k = 0; k < 64; k++) {
        float ar[4];
#pragma unroll
        for (int i = 0; i < 4; i++) ar[i] = Ps[ty * 4 + i][k];
        float4 b4 = *(const float4*)&Ws[k][tx * 4];
        float br[4] = {b4.x, b4.y, b4.z, b4.w};
#pragma unroll
        for (int i = 0; i < 4; i++)
#pragma unroll
            for (int j = 0; j < 4; j++) acc[i][j] = fmaf(ar[i], br[j], acc[i][j]);
    }

    float* target = outp ? outp : g_hB;
    float4 bias = *(const float4*)(b + tx * 4);
#pragma unroll
    for (int i = 0; i < 4; i++) {
        int gn = n0 + ty * 4 + i;
        if (gn < NN) {
            float4 o = make_float4(acc[i][0] + bias.x, acc[i][1] + bias.y,
                                   acc[i][2] + bias.z, acc[i][3] + bias.w);
            *(float4*)(target + (size_t)gn * 64 + tx * 4) = o;
        }
    }
}

// ---------------- batch norm ----------------------------------------------------
__global__ void k_bnstat() {
    __shared__ float ssum[256], ssq[256];
    int t = threadIdx.x;
    int col = t & 63, rg = t >> 6;
    float s = 0.f, q = 0.f;
    for (int row = blockIdx.x * 4 + rg; row < NN; row += gridDim.x * 4) {
        float v = g_hB[(size_t)row * 64 + col];
        s += v; q += v * v;
    }
    ssum[t] = s; ssq[t] = q; __syncthreads();
    if (t < 64) {
        float S = ssum[t] + ssum[t + 64] + ssum[t + 128] + ssum[t + 192];
        float Q = ssq[t]  + ssq[t + 64]  + ssq[t + 128]  + ssq[t + 192];
        atomicAdd(&g_bnsum[t], S);
        atomicAdd(&g_bnsq[t], Q);
    }
}

__global__ void k_bnfin(const float* __restrict__ gamma, const float* __restrict__ beta) {
    int j = threadIdx.x;
    if (j >= 64) return;
    float mu  = g_bnsum[j] / (float)NN;
    float var = g_bnsq[j] / (float)NN - mu * mu;
    float sc  = gamma[j] * rsqrtf(var + 1e-5f);
    g_bnscale[j] = sc;
    g_bnshift[j] = beta[j] - mu * sc;
}

__global__ void k_bnapply() {
    int i = blockIdx.x * blockDim.x + threadIdx.x;
    if (i >= NN * 64) return;
    int col = i & 63;
    float v = g_hB[i] * g_bnscale[col] + g_bnshift[col];
    g_hA[i] = fmaxf(v, 0.f);
}

// ---------------- launch --------------------------------------------------------
extern "C" void kernel_launch(void* const* d_in, const int* in_sizes, int n_in,
                              void* d_out, int out_size) {
    const float* x       = (const float*)d_in[0];
    const float* embed_W = (const float*)d_in[1];
    const float* embed_b = (const float*)d_in[2];
    const float* pre_W1  = (const float*)d_in[3];
    const float* pre_b1  = (const float*)d_in[4];
    const float* post_W1 = (const float*)d_in[5];
    const float* post_b1 = (const float*)d_in[6];
    const float* lin_W1  = (const float*)d_in[7];
    const float* lin_b1  = (const float*)d_in[8];
    const float* bn_g    = (const float*)d_in[9];
    const float* bn_b    = (const float*)d_in[10];
    const float* pre_W2  = (const float*)d_in[11];
    const float* pre_b2  = (const float*)d_in[12];
    const float* post_W2 = (const float*)d_in[13];
    const float* post_b2 = (const float*)d_in[14];
    const float* lin_W2  = (const float*)d_in[15];
    const float* lin_b2  = (const float*)d_in[16];
    const int*   src     = (const int*)d_in[17];
    const int*   dst     = (const int*)d_in[18];
    float* out = (float*)d_out;

    const int GN256 = (NN + 255) / 256;
    const int GE256 = NE / 256;
    const int GT64  = (NN + 63) / 64;      // 782

    // graph structure (shared by both layers)
    k_init<<<GN256, 256>>>();
    k_degree<<<GE256, 256>>>(dst);
    k_logsum<<<GN256, 256>>>();
    k_scales<<<GN256, 256>>>();
    k_scan<<<1, 1024>>>();
    k_scatter<<<GE256, 256>>>(src, dst);

    // embed
    k_embed<<<GT64, 256>>>(x, embed_W, embed_b);

    // ---- layer 1 ----
    k_preB2<<<64, 256>>>(pre_W1);
    k_hds<<<dim3(GT64, 4), 256>>>();
    k_agg<<<NN, 128>>>(pre_b1);
    k_post<<<GT64, 128>>>(post_W1, post_b1);
    k_lin<<<GT64, 256>>>(lin_W1, lin_b1, nullptr);

    // batch norm + relu -> g_hA
    k_bnstat<<<240, 256>>>();
    k_bnfin<<<1, 64>>>(bn_g, bn_b);
    k_bnapply<<<(NN * 64 + 255) / 256, 256>>>();

    // ---- layer 2 ----
    k_preB2<<<64, 256>>>(pre_W2);
    k_hds<<<dim3(GT64, 4), 256>>>();
    k_agg<<<NN, 128>>>(pre_b2);
    k_post<<<GT64, 128>>>(post_W2, post_b2);
    k_lin<<<GT64, 256>>>(lin_W2, lin_b2, out);
}

// round 8
// speedup vs baseline: 1.1718x; 1.1718x over previous
#include <cuda_runtime.h>
#include <math.h>

#define NN 50000
#define NE 800000
#define IND 128

// ---------------- scratch ------------------------------------------------------
__device__ float g_hA[NN * 64];        // layer input (embed out / post-BN)
__device__ float g_hB[NN * 64];        // layer1 lin output (pre-BN)
__device__ float g_p[NN * 64];         // post-GEMM output (pre-lin)
__device__ float g_Hd[NN * 128];       // h @ preW_top  (dst half)
__device__ float g_Hs[NN * 128];       // h @ preW_bot  (src half) — 25.6MB, L2-resident
__device__ float g_agg[NN * 512];      // per node: [t][stat(mean,min,max,std)][f]
__device__ int   g_deg[NN];
__device__ float g_invc[NN];
__device__ float g_s1[NN];
__device__ float g_s2[NN];
__device__ int   g_rowptr[NN + 1];
__device__ int   g_cursor[NN];
__device__ int   g_csrc[NE];
__device__ float g_preB2[64 * 256];    // packed [k][c]: c<128 -> top(dst), c>=128 -> bottom(src)
__device__ float g_sumlog;
__device__ float g_bnsum[64];
__device__ float g_bnsq[64];
__device__ float g_bnscale[64];
__device__ float g_bnshift[64];

// ---------------- setup --------------------------------------------------------
__global__ void k_init() {
    int i = blockIdx.x * blockDim.x + threadIdx.x;
    if (i < NN) { g_deg[i] = 0; g_cursor[i] = 0; }
    if (i == 0) g_sumlog = 0.f;
    if (i < 64) { g_bnsum[i] = 0.f; g_bnsq[i] = 0.f; }
}

__global__ void k_degree(const int* __restrict__ dst) {
    int e = blockIdx.x * blockDim.x + threadIdx.x;
    if (e < NE) atomicAdd(&g_deg[dst[e]], 1);
}

__global__ void k_logsum() {
    __shared__ float s[256];
    int i = blockIdx.x * 256 + threadIdx.x;
    float v = 0.f;
    if (i < NN) v = logf((float)g_deg[i] + 1.f);
    s[threadIdx.x] = v; __syncthreads();
    for (int o = 128; o > 0; o >>= 1) {
        if (threadIdx.x < o) s[threadIdx.x] += s[threadIdx.x + o];
        __syncthreads();
    }
    if (threadIdx.x == 0) atomicAdd(&g_sumlog, s[0]);
}

__global__ void k_scales() {
    int i = blockIdx.x * blockDim.x + threadIdx.x;
    if (i >= NN) return;
    float avg = g_sumlog / (float)NN;
    float dc  = fmaxf((float)g_deg[i], 1.f);
    g_invc[i] = 1.f / dc;
    float ld  = logf(dc + 1.f);
    g_s1[i] = ld / avg;
    g_s2[i] = avg / ld;
}

__global__ void k_scan() {
    __shared__ int ssum[1024];
    const int CH = (NN + 1023) / 1024;
    int t  = threadIdx.x;
    int lo = t * CH, hi = min(lo + CH, NN);
    int s = 0;
    for (int i = lo; i < hi; i++) s += g_deg[i];
    ssum[t] = s; __syncthreads();
    for (int o = 1; o < 1024; o <<= 1) {
        int v = (t >= o) ? ssum[t - o] : 0;
        __syncthreads();
        ssum[t] += v;
        __syncthreads();
    }
    int run = (t == 0) ? 0 : ssum[t - 1];
    for (int i = lo; i < hi; i++) { g_rowptr[i] = run; run += g_deg[i]; }
    if (t == 1023) g_rowptr[NN] = ssum[1023];
}

__global__ void k_scatter(const int* __restrict__ src, const int* __restrict__ dst) {
    int e = blockIdx.x * blockDim.x + threadIdx.x;
    if (e >= NE) return;
    int d = dst[e];
    int pos = g_rowptr[d] + atomicAdd(&g_cursor[d], 1);
    g_csrc[pos] = src[e];
}

// pack preW (T,128,64) into B[64][256]: col c: half=c>>7, j=c&127, t=j>>6, f=j&63
__global__ void k_preB2(const float* __restrict__ preW) {
    int i = blockIdx.x * blockDim.x + threadIdx.x;
    if (i >= 64 * 256) return;
    int k = i >> 8, c = i & 255;
    int half = c >> 7, j = c & 127;
    int t = j >> 6, f = j & 63;
    g_preB2[i] = preW[t * 8192 + (half * 64 + k) * 64 + f];
}

// ---------------- embed GEMM: h = x @ W + b  (K=128, N=64) ----------------------
__global__ __launch_bounds__(256) void k_embed(const float* __restrict__ x,
                                               const float* __restrict__ W,
                                               const float* __restrict__ b) {
    __shared__ float Xs[128][64];
    __shared__ float Ws[128][64];
    int t  = threadIdx.x;
    int n0 = blockIdx.x * 64;

    for (int i = t; i < 2048; i += 256)
        ((float4*)Ws)[i] = ((const float4*)W)[i];

    int row = t & 63, kq = t >> 6;
    int gr = n0 + row;
#pragma unroll
    for (int j = 0; j < 8; j++) {
        int k = kq * 32 + j * 4;
        float4 v = make_float4(0.f, 0.f, 0.f, 0.f);
        if (gr < NN) v = *(const float4*)(x + (size_t)gr * IND + k);
        Xs[k][row] = v.x; Xs[k + 1][row] = v.y; Xs[k + 2][row] = v.z; Xs[k + 3][row] = v.w;
    }
    __syncthreads();

    int tx = t & 15, ty = t >> 4;
    float acc[4][4];
#pragma unroll
    for (int i = 0; i < 4; i++)
#pragma unroll
        for (int j = 0; j < 4; j++) acc[i][j] = 0.f;

#pragma unroll 8
    for (int k = 0; k < 128; k++) {
        float4 a  = *(const float4*)&Xs[k][ty * 4];
        float4 b4 = *(const float4*)&Ws[k][tx * 4];
        float ar[4] = {a.x, a.y, a.z, a.w};
        float br[4] = {b4.x, b4.y, b4.z, b4.w};
#pragma unroll
        for (int i = 0; i < 4; i++)
#pragma unroll
            for (int j = 0; j < 4; j++) acc[i][j] = fmaf(ar[i], br[j], acc[i][j]);
    }

    float4 bias = *(const float4*)(b + tx * 4);
#pragma unroll
    for (int i = 0; i < 4; i++) {
        int gn = n0 + ty * 4 + i;
        if (gn < NN) {
            float4 o = make_float4(acc[i][0] + bias.x, acc[i][1] + bias.y,
                                   acc[i][2] + bias.z, acc[i][3] + bias.w);
            *(float4*)(g_hA + (size_t)gn * 64 + tx * 4) = o;
        }
    }
}

// ---------------- Hd/Hs GEMM: [Hd|Hs] = h @ preB2  (K=64, N=256) ----------------
// One block per 64-node tile; loops over the 4 column groups reusing Xs.
__global__ __launch_bounds__(256) void k_hds() {
    __shared__ float Xs[64][64];   // [k][node]
    __shared__ float Bs[64][64];   // [k][c]
    int t  = threadIdx.x;
    int n0 = blockIdx.x * 64;

    int node = t & 63, kq = t >> 6;
    int gr = n0 + node;
#pragma unroll
    for (int j = 0; j < 4; j++) {
        int k = kq * 16 + j * 4;
        float4 v = make_float4(0.f, 0.f, 0.f, 0.f);
        if (gr < NN) v = *(const float4*)(g_hA + (size_t)gr * 64 + k);
        Xs[k][node] = v.x; Xs[k + 1][node] = v.y; Xs[k + 2][node] = v.z; Xs[k + 3][node] = v.w;
    }

    int tx = t & 15, ty = t >> 4;

    for (int cg = 0; cg < 4; cg++) {
        __syncthreads();   // Xs ready (cg=0) / previous Bs fully consumed
#pragma unroll
        for (int i = 0; i < 4; i++) {
            int u = t + 256 * i;
            int k = u >> 4, cq = u & 15;
            *(float4*)&Bs[k][cq * 4] = *(const float4*)(g_preB2 + k * 256 + cg * 64 + cq * 4);
        }
        __syncthreads();

        float acc[4][4];
#pragma unroll
        for (int i = 0; i < 4; i++)
#pragma unroll
            for (int j = 0; j < 4; j++) acc[i][j] = 0.f;

#pragma unroll 8
        for (int k = 0; k < 64; k++) {
            float4 a  = *(const float4*)&Xs[k][ty * 4];
            float4 b4 = *(const float4*)&Bs[k][tx * 4];
            float ar[4] = {a.x, a.y, a.z, a.w};
            float br[4] = {b4.x, b4.y, b4.z, b4.w};
#pragma unroll
            for (int i = 0; i < 4; i++)
#pragma unroll
                for (int j = 0; j < 4; j++) acc[i][j] = fmaf(ar[i], br[j], acc[i][j]);
        }

        int c0 = cg * 64 + tx * 4;
#pragma unroll
        for (int i = 0; i < 4; i++) {
            int gn = n0 + ty * 4 + i;
            if (gn < NN) {
                float4 o = make_float4(acc[i][0], acc[i][1], acc[i][2], acc[i][3]);
                if (c0 < 128) *(float4*)(g_Hd + (size_t)gn * 128 + c0) = o;
                else          *(float4*)(g_Hs + (size_t)gn * 128 + (c0 - 128)) = o;
            }
        }
    }
}

// ---------------- fused gather+aggregate (2 nodes per block) --------------------
// m[e] = c_n + s_e  where c_n = Hd[n]+preb (const per node), s_e = Hs[src[e]].
// mean(m)=c+mean(s); min(m)=c+min(s); max(m)=c+max(s); std(m)=std(s).
__global__ __launch_bounds__(256) void k_agg(const float* __restrict__ preb) {
    int n = blockIdx.x * 2 + (threadIdx.x >> 7);
    int f = threadIdx.x & 127;     // 0..127
    int lo = g_rowptr[n], hi = g_rowptr[n + 1];
    float sum = 0.f, sq = 0.f;
    float mn = INFINITY, mx = -INFINITY;
    int p = lo;
    for (; p + 4 <= hi; p += 4) {
        int i0 = g_csrc[p], i1 = g_csrc[p + 1], i2 = g_csrc[p + 2], i3 = g_csrc[p + 3];
        float v0 = g_Hs[(size_t)i0 * 128 + f];
        float v1 = g_Hs[(size_t)i1 * 128 + f];
        float v2 = g_Hs[(size_t)i2 * 128 + f];
        float v3 = g_Hs[(size_t)i3 * 128 + f];
        sum += (v0 + v1) + (v2 + v3);
        sq  = fmaf(v0, v0, fmaf(v1, v1, fmaf(v2, v2, fmaf(v3, v3, sq))));
        mn = fminf(mn, fminf(fminf(v0, v1), fminf(v2, v3)));
        mx = fmaxf(mx, fmaxf(fmaxf(v0, v1), fmaxf(v2, v3)));
    }
    for (; p < hi; p++) {
        float v = g_Hs[(size_t)g_csrc[p] * 128 + f];
        sum += v; sq = fmaf(v, v, sq);
        mn = fminf(mn, v); mx = fmaxf(mx, v);
    }
    float c = g_Hd[(size_t)n * 128 + f] + preb[f];
    int deg = hi - lo;
    float mean, mnO, mxO, sd;
    if (deg > 0) {
        float invc = g_invc[n];
        float ms  = sum * invc;
        float var = sq * invc - ms * ms;
        mean = c + ms; mnO = c + mn; mxO = c + mx;
        sd = sqrtf(fmaxf(var, 0.f) + 1e-5f);
    } else {
        mean = 0.f; mnO = 0.f; mxO = 0.f; sd = sqrtf(1e-5f);
    }
    int tt = f >> 6, ff = f & 63;
    size_t base = (size_t)n * 512 + tt * 256 + ff;
    g_agg[base]       = mean;
    g_agg[base + 64]  = mnO;
    g_agg[base + 128] = mxO;
    g_agg[base + 192] = sd;
}

// ---------------- post GEMM (R6-proven): 64 nodes x 64 cols, 256 thr, 4x4 -------
// K = 832 per tower (h 64 | agg 256 | agg*s1 256 | agg*s2 256), 13 chunks of 64.
__global__ __launch_bounds__(256) void k_post(const float* __restrict__ postW,
                                              const float* __restrict__ postb) {
    __shared__ float A13[2][64][68];   // [tower][node][k]  — 34816 B
    __shared__ float Ws[64][64];       // [kk][c], c = t*32+g — 16384 B
    int t  = threadIdx.x;
    int n0 = blockIdx.x * 64;
    int tx = t & 15, ty = t >> 4;
    int tc = tx >> 3;                  // tower for this thread's columns

    float acc[4][4];
#pragma unroll
    for (int i = 0; i < 4; i++)
#pragma unroll
        for (int j = 0; j < 4; j++) acc[i][j] = 0.f;

    for (int ci = 0; ci < 13; ci++) {
        int kc = ci * 64;
        float4 va[8];
#pragma unroll
        for (int i = 0; i < 8; i++) {
            int u = t + 256 * i;
            int tw = u >> 10, node = (u >> 4) & 63, kq = u & 15;
            int gn = n0 + node;
            float4 v = make_float4(0.f, 0.f, 0.f, 0.f);
            if (gn < NN) {
                if (ci == 0) {
                    v = *(const float4*)(g_hA + (size_t)gn * 64 + kq * 4);
                } else {
                    int k = kc + kq * 4;
                    int j; float s = 1.f;
                    if (ci < 5)      { j = k - 64; }
                    else if (ci < 9) { j = k - 320; s = g_s1[gn]; }
                    else             { j = k - 576; s = g_s2[gn]; }
                    v = *(const float4*)(g_agg + (size_t)gn * 512 + tw * 256 + j);
                    v.x *= s; v.y *= s; v.z *= s; v.w *= s;
                }
            }
            va[i] = v;
        }
        float4 vb[4];
#pragma unroll
        for (int i = 0; i < 4; i++) {
            int u = t + 256 * i;
            int kk = u >> 4, cq = u & 15;
            int tw = cq >> 3, g = (cq * 4) & 31;
            vb[i] = *(const float4*)(postW + tw * 26624 + (kc + kk) * 32 + g);
        }
        __syncthreads();
#pragma unroll
        for (int i = 0; i < 8; i++) {
            int u = t + 256 * i;
            int tw = u >> 10, node = (u >> 4) & 63, kq = u & 15;
            *(float4*)&A13[tw][node][kq * 4] = va[i];
        }
#pragma unroll
        for (int i = 0; i < 4; i++) ((float4*)Ws)[t + 256 * i] = vb[i];
        __syncthreads();

#pragma unroll 8
        for (int kk = 0; kk < 64; kk++) {
            float ar[4];
#pragma unroll
            for (int i = 0; i < 4; i++) ar[i] = A13[tc][ty * 4 + i][kk];
            float4 b4 = *(const float4*)&Ws[kk][tx * 4];
            float br[4] = {b4.x, b4.y, b4.z, b4.w};
#pragma unroll
            for (int i = 0; i < 4; i++)
#pragma unroll
                for (int j = 0; j < 4; j++) acc[i][j] = fmaf(ar[i], br[j], acc[i][j]);
        }
        __syncthreads();
    }

    float4 bias = *(const float4*)(postb + tx * 4);
#pragma unroll
    for (int i = 0; i < 4; i++) {
        int gn = n0 + ty * 4 + i;
        if (gn < NN) {
            float4 o = make_float4(acc[i][0] + bias.x, acc[i][1] + bias.y,
                                   acc[i][2] + bias.z, acc[i][3] + bias.w);
            *(float4*)(g_p + (size_t)gn * 64 + tx * 4) = o;
        }
    }
}

// ---------------- lin GEMM: out = P @ linW + linb (K=64) ------------------------
// Layer 1 (outp==nullptr): also accumulates BN column stats (sum, sumsq).
__global__ __launch_bounds__(256) void k_lin(const float* __restrict__ W,
                                             const float* __restrict__ b,
                                             float* __restrict__ outp) {
    __shared__ float Ps[64][68];
    __shared__ float Ws[64][64];
    int t  = threadIdx.x;
    int n0 = blockIdx.x * 64;

    for (int i = t; i < 1024; i += 256) ((float4*)Ws)[i] = ((const float4*)W)[i];
#pragma unroll
    for (int i = 0; i < 4; i++) {
        int u = t + 256 * i;
        int node = u >> 4, kq = u & 15;
        int gn = n0 + node;
        float4 v = make_float4(0.f, 0.f, 0.f, 0.f);
        if (gn < NN) v = *(const float4*)(g_p + (size_t)gn * 64 + kq * 4);
        *(float4*)&Ps[node][kq * 4] = v;
    }
    __syncthreads();

    int tx = t & 15, ty = t >> 4;
    float acc[4][4];
#pragma unroll
    for (int i = 0; i < 4; i++)
#pragma unroll
        for (int j = 0; j < 4; j++) acc[i][j] = 0.f;

#pragma unroll 8
    for (int k = 0; k < 64; k++) {
        float ar[4];
#pragma unroll
        for (int i = 0; i < 4; i++) ar[i] = Ps[ty * 4 + i][k];
        float4 b4 = *(const float4*)&Ws[k][tx * 4];
        float br[4] = {b4.x, b4.y, b4.z, b4.w};
#pragma unroll
        for (int i = 0; i < 4; i++)
#pragma unroll
            for (int j = 0; j < 4; j++) acc[i][j] = fmaf(ar[i], br[j], acc[i][j]);
    }

    float* target = outp ? outp : g_hB;
    float4 bias = *(const float4*)(b + tx * 4);
    float lsum[4] = {0.f, 0.f, 0.f, 0.f};
    float lsq[4]  = {0.f, 0.f, 0.f, 0.f};
#pragma unroll
    for (int i = 0; i < 4; i++) {
        int gn = n0 + ty * 4 + i;
        if (gn < NN) {
            float o0 = acc[i][0] + bias.x, o1 = acc[i][1] + bias.y;
            float o2 = acc[i][2] + bias.z, o3 = acc[i][3] + bias.w;
            *(float4*)(target + (size_t)gn * 64 + tx * 4) = make_float4(o0, o1, o2, o3);
            lsum[0] += o0; lsum[1] += o1; lsum[2] += o2; lsum[3] += o3;
            lsq[0] = fmaf(o0, o0, lsq[0]); lsq[1] = fmaf(o1, o1, lsq[1]);
            lsq[2] = fmaf(o2, o2, lsq[2]); lsq[3] = fmaf(o3, o3, lsq[3]);
        }
    }

    if (!outp) {   // fused BN stats (layer 1)
        __syncthreads();
        float* redS = &Ps[0][0];     // 16 x 68 area
        float* redQ = &Ws[0][0];     // 16 x 68 area
#pragma unroll
        for (int j = 0; j < 4; j++) {
            redS[ty * 68 + tx * 4 + j] = lsum[j];
            redQ[ty * 68 + tx * 4 + j] = lsq[j];
        }
        __syncthreads();
        for (int o = 8; o > 0; o >>= 1) {
            if (ty < o) {
#pragma unroll
                for (int j = 0; j < 4; j++) {
                    redS[ty * 68 + tx * 4 + j] += redS[(ty + o) * 68 + tx * 4 + j];
                    redQ[ty * 68 + tx * 4 + j] += redQ[(ty + o) * 68 + tx * 4 + j];
                }
            }
            __syncthreads();
        }
        if (ty == 0) {
#pragma unroll
            for (int j = 0; j < 4; j++) {
                atomicAdd(&g_bnsum[tx * 4 + j], redS[tx * 4 + j]);
                atomicAdd(&g_bnsq[tx * 4 + j],  redQ[tx * 4 + j]);
            }
        }
    }
}

// ---------------- batch norm ----------------------------------------------------
__global__ void k_bnfin(const float* __restrict__ gamma, const float* __restrict__ beta) {
    int j = threadIdx.x;
    if (j >= 64) return;
    float mu  = g_bnsum[j] / (float)NN;
    float var = g_bnsq[j] / (float)NN - mu * mu;
    float sc  = gamma[j] * rsqrtf(var + 1e-5f);
    g_bnscale[j] = sc;
    g_bnshift[j] = beta[j] - mu * sc;
}

__global__ void k_bnapply() {
    int i = blockIdx.x * blockDim.x + threadIdx.x;
    if (i >= NN * 64) return;
    int col = i & 63;
    float v = g_hB[i] * g_bnscale[col] + g_bnshift[col];
    g_hA[i] = fmaxf(v, 0.f);
}

// ---------------- launch --------------------------------------------------------
extern "C" void kernel_launch(void* const* d_in, const int* in_sizes, int n_in,
                              void* d_out, int out_size) {
    const float* x       = (const float*)d_in[0];
    const float* embed_W = (const float*)d_in[1];
    const float* embed_b = (const float*)d_in[2];
    const float* pre_W1  = (const float*)d_in[3];
    const float* pre_b1  = (const float*)d_in[4];
    const float* post_W1 = (const float*)d_in[5];
    const float* post_b1 = (const float*)d_in[6];
    const float* lin_W1  = (const float*)d_in[7];
    const float* lin_b1  = (const float*)d_in[8];
    const float* bn_g    = (const float*)d_in[9];
    const float* bn_b    = (const float*)d_in[10];
    const float* pre_W2  = (const float*)d_in[11];
    const float* pre_b2  = (const float*)d_in[12];
    const float* post_W2 = (const float*)d_in[13];
    const float* post_b2 = (const float*)d_in[14];
    const float* lin_W2  = (const float*)d_in[15];
    const float* lin_b2  = (const float*)d_in[16];
    const int*   src     = (const int*)d_in[17];
    const int*   dst     = (const int*)d_in[18];
    float* out = (float*)d_out;

    const int GN256 = (NN + 255) / 256;
    const int GE256 = NE / 256;
    const int GT64  = (NN + 63) / 64;      // 782

    // graph structure (shared by both layers)
    k_init<<<GN256, 256>>>();
    k_degree<<<GE256, 256>>>(dst);
    k_logsum<<<GN256, 256>>>();
    k_scales<<<GN256, 256>>>();
    k_scan<<<1, 1024>>>();
    k_scatter<<<GE256, 256>>>(src, dst);

    // embed
    k_embed<<<GT64, 256>>>(x, embed_W, embed_b);

    // ---- layer 1 ----
    k_preB2<<<64, 256>>>(pre_W1);
    k_hds<<<GT64, 256>>>();
    k_agg<<<NN / 2, 256>>>(pre_b1);
    k_post<<<GT64, 256>>>(post_W1, post_b1);
    k_lin<<<GT64, 256>>>(lin_W1, lin_b1, nullptr);   // fused BN stats

    // batch norm + relu -> g_hA
    k_bnfin<<<1, 64>>>(bn_g, bn_b);
    k_bnapply<<<(NN * 64 + 255) / 256, 256>>>();

    // ---- layer 2 ----
    k_preB2<<<64, 256>>>(pre_W2);
    k_hds<<<GT64, 256>>>();
    k_agg<<<NN / 2, 256>>>(pre_b2);
    k_post<<<GT64, 256>>>(post_W2, post_b2);
    k_lin<<<GT64, 256>>>(lin_W2, lin_b2, out);
}

// round 9
// speedup vs baseline: 1.2055x; 1.0287x over previous
#include <cuda_runtime.h>
#include <math.h>

#define NN 50000
#define NE 800000
#define IND 128

// ---------------- scratch ------------------------------------------------------
__device__ float g_hA[NN * 64];        // layer input (embed out / post-BN)
__device__ float g_hB[NN * 64];        // layer1 output (pre-BN)
__device__ float g_Hd[NN * 128];       // h @ preW_top  (dst half)
__device__ float g_Hs[NN * 128];       // h @ preW_bot  (src half) — 25.6MB, L2-resident
__device__ float g_agg[NN * 512];      // per node: [t][stat(mean,min,max,std)][f]
__device__ int   g_deg[NN];
__device__ float g_invc[NN];
__device__ float g_s1[NN];
__device__ float g_s2[NN];
__device__ int   g_rowptr[NN + 1];
__device__ int   g_cursor[NN];
__device__ int   g_csrc[NE];
__device__ float g_preB2a[64 * 256];   // layer1 packed preW  [k][c]
__device__ float g_preB2b[64 * 256];   // layer2 packed preW  [k][c]
__device__ float g_sumlog;
__device__ float g_bnsum[64];
__device__ float g_bnsq[64];
__device__ float g_bnscale[64];
__device__ float g_bnshift[64];

// ---------------- setup --------------------------------------------------------
__global__ void k_init() {
    int i = blockIdx.x * blockDim.x + threadIdx.x;
    if (i < NN) { g_deg[i] = 0; g_cursor[i] = 0; }
    if (i == 0) g_sumlog = 0.f;
    if (i < 64) { g_bnsum[i] = 0.f; g_bnsq[i] = 0.f; }
}

__global__ void k_degree(const int* __restrict__ dst) {
    int e = blockIdx.x * blockDim.x + threadIdx.x;
    if (e < NE) atomicAdd(&g_deg[dst[e]], 1);
}

__global__ void k_logsum() {
    __shared__ float s[256];
    int i = blockIdx.x * 256 + threadIdx.x;
    float v = 0.f;
    if (i < NN) v = logf((float)g_deg[i] + 1.f);
    s[threadIdx.x] = v; __syncthreads();
    for (int o = 128; o > 0; o >>= 1) {
        if (threadIdx.x < o) s[threadIdx.x] += s[threadIdx.x + o];
        __syncthreads();
    }
    if (threadIdx.x == 0) atomicAdd(&g_sumlog, s[0]);
}

__global__ void k_scales() {
    int i = blockIdx.x * blockDim.x + threadIdx.x;
    if (i >= NN) return;
    float avg = g_sumlog / (float)NN;
    float dc  = fmaxf((float)g_deg[i], 1.f);
    g_invc[i] = 1.f / dc;
    float ld  = logf(dc + 1.f);
    g_s1[i] = ld / avg;
    g_s2[i] = avg / ld;
}

__global__ void k_scan() {
    __shared__ int ssum[1024];
    const int CH = (NN + 1023) / 1024;
    int t  = threadIdx.x;
    int lo = t * CH, hi = min(lo + CH, NN);
    int s = 0;
    for (int i = lo; i < hi; i++) s += g_deg[i];
    ssum[t] = s; __syncthreads();
    for (int o = 1; o < 1024; o <<= 1) {
        int v = (t >= o) ? ssum[t - o] : 0;
        __syncthreads();
        ssum[t] += v;
        __syncthreads();
    }
    int run = (t == 0) ? 0 : ssum[t - 1];
    for (int i = lo; i < hi; i++) { g_rowptr[i] = run; run += g_deg[i]; }
    if (t == 1023) g_rowptr[NN] = ssum[1023];
}

__global__ void k_scatter(const int* __restrict__ src, const int* __restrict__ dst) {
    int e = blockIdx.x * blockDim.x + threadIdx.x;
    if (e >= NE) return;
    int d = dst[e];
    int pos = g_rowptr[d] + atomicAdd(&g_cursor[d], 1);
    g_csrc[pos] = src[e];
}

// pack both layers' preW (T,128,64) into [64][256]: col c: half=c>>7, j=c&127
__global__ void k_preB2both(const float* __restrict__ preW1,
                            const float* __restrict__ preW2) {
    int i = blockIdx.x * blockDim.x + threadIdx.x;
    if (i >= 2 * 64 * 256) return;
    int which = i >> 14;               // 0: layer1, 1: layer2
    int u = i & 16383;
    int k = u >> 8, c = u & 255;
    int half = c >> 7, j = c & 127;
    int t = j >> 6, f = j & 63;
    const float* w = which ? preW2 : preW1;
    float* o = which ? g_preB2b : g_preB2a;
    o[u] = w[t * 8192 + (half * 64 + k) * 64 + f];
}

// ---------------- embed GEMM: h = x @ W + b  (K=128, N=64) ----------------------
__global__ __launch_bounds__(256) void k_embed(const float* __restrict__ x,
                                               const float* __restrict__ W,
                                               const float* __restrict__ b) {
    __shared__ float Xs[128][64];
    __shared__ float Ws[128][64];
    int t  = threadIdx.x;
    int n0 = blockIdx.x * 64;

    for (int i = t; i < 2048; i += 256)
        ((float4*)Ws)[i] = ((const float4*)W)[i];

    int row = t & 63, kq = t >> 6;
    int gr = n0 + row;
#pragma unroll
    for (int j = 0; j < 8; j++) {
        int k = kq * 32 + j * 4;
        float4 v = make_float4(0.f, 0.f, 0.f, 0.f);
        if (gr < NN) v = *(const float4*)(x + (size_t)gr * IND + k);
        Xs[k][row] = v.x; Xs[k + 1][row] = v.y; Xs[k + 2][row] = v.z; Xs[k + 3][row] = v.w;
    }
    __syncthreads();

    int tx = t & 15, ty = t >> 4;
    float acc[4][4];
#pragma unroll
    for (int i = 0; i < 4; i++)
#pragma unroll
        for (int j = 0; j < 4; j++) acc[i][j] = 0.f;

#pragma unroll 8
    for (int k = 0; k < 128; k++) {
        float4 a  = *(const float4*)&Xs[k][ty * 4];
        float4 b4 = *(const float4*)&Ws[k][tx * 4];
        float ar[4] = {a.x, a.y, a.z, a.w};
        float br[4] = {b4.x, b4.y, b4.z, b4.w};
#pragma unroll
        for (int i = 0; i < 4; i++)
#pragma unroll
            for (int j = 0; j < 4; j++) acc[i][j] = fmaf(ar[i], br[j], acc[i][j]);
    }

    float4 bias = *(const float4*)(b + tx * 4);
#pragma unroll
    for (int i = 0; i < 4; i++) {
        int gn = n0 + ty * 4 + i;
        if (gn < NN) {
            float4 o = make_float4(acc[i][0] + bias.x, acc[i][1] + bias.y,
                                   acc[i][2] + bias.z, acc[i][3] + bias.w);
            *(float4*)(g_hA + (size_t)gn * 64 + tx * 4) = o;
        }
    }
}

// ---------------- Hd/Hs GEMM: [Hd|Hs] = h @ preB2  (K=64, N=256) ----------------
// layer==1: applies BN (scale/shift) + ReLU to g_hB during the Xs load and
// writes the activated values back to g_hA (replaces the separate bnapply pass).
__global__ __launch_bounds__(256) void k_hds(int layer) {
    __shared__ float Xs[64][64];   // [k][node]
    __shared__ float Bs[64][64];   // [k][c]
    int t  = threadIdx.x;
    int n0 = blockIdx.x * 64;
    const float* preB = layer ? g_preB2b : g_preB2a;

    int node = t & 63, kq = t >> 6;
    int gr = n0 + node;
#pragma unroll
    for (int j = 0; j < 4; j++) {
        int k = kq * 16 + j * 4;
        float4 v = make_float4(0.f, 0.f, 0.f, 0.f);
        if (gr < NN) {
            if (layer == 0) {
                v = *(const float4*)(g_hA + (size_t)gr * 64 + k);
            } else {
                float4 hv = *(const float4*)(g_hB + (size_t)gr * 64 + k);
                v.x = fmaxf(hv.x * g_bnscale[k]     + g_bnshift[k],     0.f);
                v.y = fmaxf(hv.y * g_bnscale[k + 1] + g_bnshift[k + 1], 0.f);
                v.z = fmaxf(hv.z * g_bnscale[k + 2] + g_bnshift[k + 2], 0.f);
                v.w = fmaxf(hv.w * g_bnscale[k + 3] + g_bnshift[k + 3], 0.f);
                *(float4*)(g_hA + (size_t)gr * 64 + k) = v;   // layer-2 h input
            }
        }
        Xs[k][node] = v.x; Xs[k + 1][node] = v.y; Xs[k + 2][node] = v.z; Xs[k + 3][node] = v.w;
    }

    int tx = t & 15, ty = t >> 4;

    for (int cg = 0; cg < 4; cg++) {
        __syncthreads();   // Xs ready (cg=0) / previous Bs fully consumed
#pragma unroll
        for (int i = 0; i < 4; i++) {
            int u = t + 256 * i;
            int k = u >> 4, cq = u & 15;
            *(float4*)&Bs[k][cq * 4] = *(const float4*)(preB + k * 256 + cg * 64 + cq * 4);
        }
        __syncthreads();

        float acc[4][4];
#pragma unroll
        for (int i = 0; i < 4; i++)
#pragma unroll
            for (int j = 0; j < 4; j++) acc[i][j] = 0.f;

#pragma unroll 8
        for (int k = 0; k < 64; k++) {
            float4 a  = *(const float4*)&Xs[k][ty * 4];
            float4 b4 = *(const float4*)&Bs[k][tx * 4];
            float ar[4] = {a.x, a.y, a.z, a.w};
            float br[4] = {b4.x, b4.y, b4.z, b4.w};
#pragma unroll
            for (int i = 0; i < 4; i++)
#pragma unroll
                for (int j = 0; j < 4; j++) acc[i][j] = fmaf(ar[i], br[j], acc[i][j]);
        }

        int c0 = cg * 64 + tx * 4;
#pragma unroll
        for (int i = 0; i < 4; i++) {
            int gn = n0 + ty * 4 + i;
            if (gn < NN) {
                float4 o = make_float4(acc[i][0], acc[i][1], acc[i][2], acc[i][3]);
                if (c0 < 128) *(float4*)(g_Hd + (size_t)gn * 128 + c0) = o;
                else          *(float4*)(g_Hs + (size_t)gn * 128 + (c0 - 128)) = o;
            }
        }
    }
}

// ---------------- fused gather+aggregate (2 nodes per block) --------------------
// m[e] = c_n + s_e  where c_n = Hd[n]+preb (const per node), s_e = Hs[src[e]].
// mean(m)=c+mean(s); min(m)=c+min(s); max(m)=c+max(s); std(m)=std(s).
__global__ __launch_bounds__(256) void k_agg(const float* __restrict__ preb) {
    int n = blockIdx.x * 2 + (threadIdx.x >> 7);
    int f = threadIdx.x & 127;     // 0..127
    int lo = g_rowptr[n], hi = g_rowptr[n + 1];
    float sum = 0.f, sq = 0.f;
    float mn = INFINITY, mx = -INFINITY;
    int p = lo;
    for (; p + 4 <= hi; p += 4) {
        int i0 = g_csrc[p], i1 = g_csrc[p + 1], i2 = g_csrc[p + 2], i3 = g_csrc[p + 3];
        float v0 = g_Hs[(size_t)i0 * 128 + f];
        float v1 = g_Hs[(size_t)i1 * 128 + f];
        float v2 = g_Hs[(size_t)i2 * 128 + f];
        float v3 = g_Hs[(size_t)i3 * 128 + f];
        sum += (v0 + v1) + (v2 + v3);
        sq  = fmaf(v0, v0, fmaf(v1, v1, fmaf(v2, v2, fmaf(v3, v3, sq))));
        mn = fminf(mn, fminf(fminf(v0, v1), fminf(v2, v3)));
        mx = fmaxf(mx, fmaxf(fmaxf(v0, v1), fmaxf(v2, v3)));
    }
    for (; p < hi; p++) {
        float v = g_Hs[(size_t)g_csrc[p] * 128 + f];
        sum += v; sq = fmaf(v, v, sq);
        mn = fminf(mn, v); mx = fmaxf(mx, v);
    }
    float c = g_Hd[(size_t)n * 128 + f] + preb[f];
    int deg = hi - lo;
    float mean, mnO, mxO, sd;
    if (deg > 0) {
        float invc = g_invc[n];
        float ms  = sum * invc;
        float var = sq * invc - ms * ms;
        mean = c + ms; mnO = c + mn; mxO = c + mx;
        sd = sqrtf(fmaxf(var, 0.f) + 1e-5f);
    } else {
        mean = 0.f; mnO = 0.f; mxO = 0.f; sd = sqrtf(1e-5f);
    }
    int tt = f >> 6, ff = f & 63;
    size_t base = (size_t)n * 512 + tt * 256 + ff;
    g_agg[base]       = mean;
    g_agg[base + 64]  = mnO;
    g_agg[base + 128] = mxO;
    g_agg[base + 192] = sd;
}

// ---------------- fused post+lin GEMM -------------------------------------------
// Stage 1 (proven R6 tile): P[64 nodes][64 cols] over K=832 (13 chunks of 64).
// Stage 2: out = P @ linW + linb in-block (K=64, same 4x4 pattern).
// Layer 1 (outp==nullptr): writes g_hB and accumulates BN column stats.
__global__ __launch_bounds__(256) void k_postlin(const float* __restrict__ postW,
                                                 const float* __restrict__ postb,
                                                 const float* __restrict__ linW,
                                                 const float* __restrict__ linb,
                                                 float* __restrict__ outp) {
    __shared__ float A13[2][64][68];   // [tower][node][k]  — 34816 B
    __shared__ float Ws[64][64];       // weights tile       — 16384 B
    int t  = threadIdx.x;
    int n0 = blockIdx.x * 64;
    int tx = t & 15, ty = t >> 4;
    int tc = tx >> 3;                  // tower for this thread's columns

    float acc[4][4];
#pragma unroll
    for (int i = 0; i < 4; i++)
#pragma unroll
        for (int j = 0; j < 4; j++) acc[i][j] = 0.f;

    for (int ci = 0; ci < 13; ci++) {
        int kc = ci * 64;
        float4 va[8];
#pragma unroll
        for (int i = 0; i < 8; i++) {
            int u = t + 256 * i;
            int tw = u >> 10, node = (u >> 4) & 63, kq = u & 15;
            int gn = n0 + node;
            float4 v = make_float4(0.f, 0.f, 0.f, 0.f);
            if (gn < NN) {
                if (ci == 0) {
                    v = *(const float4*)(g_hA + (size_t)gn * 64 + kq * 4);
                } else {
                    int k = kc + kq * 4;
                    int j; float s = 1.f;
                    if (ci < 5)      { j = k - 64; }
                    else if (ci < 9) { j = k - 320; s = g_s1[gn]; }
                    else             { j = k - 576; s = g_s2[gn]; }
                    v = *(const float4*)(g_agg + (size_t)gn * 512 + tw * 256 + j);
                    v.x *= s; v.y *= s; v.z *= s; v.w *= s;
                }
            }
            va[i] = v;
        }
        float4 vb[4];
#pragma unroll
        for (int i = 0; i < 4; i++) {
            int u = t + 256 * i;
            int kk = u >> 4, cq = u & 15;
            int tw = cq >> 3, g = (cq * 4) & 31;
            vb[i] = *(const float4*)(postW + tw * 26624 + (kc + kk) * 32 + g);
        }
        __syncthreads();
#pragma unroll
        for (int i = 0; i < 8; i++) {
            int u = t + 256 * i;
            int tw = u >> 10, node = (u >> 4) & 63, kq = u & 15;
            *(float4*)&A13[tw][node][kq * 4] = va[i];
        }
#pragma unroll
        for (int i = 0; i < 4; i++) ((float4*)Ws)[t + 256 * i] = vb[i];
        __syncthreads();

#pragma unroll 8
        for (int kk = 0; kk < 64; kk++) {
            float ar[4];
#pragma unroll
            for (int i = 0; i < 4; i++) ar[i] = A13[tc][ty * 4 + i][kk];
            float4 b4 = *(const float4*)&Ws[kk][tx * 4];
            float br[4] = {b4.x, b4.y, b4.z, b4.w};
#pragma unroll
            for (int i = 0; i < 4; i++)
#pragma unroll
                for (int j = 0; j < 4; j++) acc[i][j] = fmaf(ar[i], br[j], acc[i][j]);
        }
        __syncthreads();
    }

    // -------- stage 2: P-tile -> smem, multiply by linW --------
    float (*Ptile)[68] = A13[0];       // 64 x 68
    float4 pbias = *(const float4*)(postb + tx * 4);
#pragma unroll
    for (int i = 0; i < 4; i++) {
        Ptile[ty * 4 + i][tx * 4 + 0] = acc[i][0] + pbias.x;
        Ptile[ty * 4 + i][tx * 4 + 1] = acc[i][1] + pbias.y;
        Ptile[ty * 4 + i][tx * 4 + 2] = acc[i][2] + pbias.z;
        Ptile[ty * 4 + i][tx * 4 + 3] = acc[i][3] + pbias.w;
    }
#pragma unroll
    for (int i = 0; i < 4; i++)
        ((float4*)Ws)[t + 256 * i] = ((const float4*)linW)[t + 256 * i];
    __syncthreads();

    float acc2[4][4];
#pragma unroll
    for (int i = 0; i < 4; i++)
#pragma unroll
        for (int j = 0; j < 4; j++) acc2[i][j] = 0.f;

#pragma unroll 8
    for (int k = 0; k < 64; k++) {
        float ar[4];
#pragma unroll
        for (int i = 0; i < 4; i++) ar[i] = Ptile[ty * 4 + i][k];
        float4 b4 = *(const float4*)&Ws[k][tx * 4];
        float br[4] = {b4.x, b4.y, b4.z, b4.w};
#pragma unroll
        for (int i = 0; i < 4; i++)
#pragma unroll
            for (int j = 0; j < 4; j++) acc2[i][j] = fmaf(ar[i], br[j], acc2[i][j]);
    }

    float* target = outp ? outp : g_hB;
    float4 lbias = *(const float4*)(linb + tx * 4);
    float lsum[4] = {0.f, 0.f, 0.f, 0.f};
    float lsq[4]  = {0.f, 0.f, 0.f, 0.f};
#pragma unroll
    for (int i = 0; i < 4; i++) {
        int gn = n0 + ty * 4 + i;
        if (gn < NN) {
            float o0 = acc2[i][0] + lbias.x, o1 = acc2[i][1] + lbias.y;
            float o2 = acc2[i][2] + lbias.z, o3 = acc2[i][3] + lbias.w;
            *(float4*)(target + (size_t)gn * 64 + tx * 4) = make_float4(o0, o1, o2, o3);
            lsum[0] += o0; lsum[1] += o1; lsum[2] += o2; lsum[3] += o3;
            lsq[0] = fmaf(o0, o0, lsq[0]); lsq[1] = fmaf(o1, o1, lsq[1]);
            lsq[2] = fmaf(o2, o2, lsq[2]); lsq[3] = fmaf(o3, o3, lsq[3]);
        }
    }

    if (!outp) {   // fused BN stats (layer 1)
        __syncthreads();
        float* redS = &A13[1][0][0];
        float* redQ = &Ws[0][0];
#pragma unroll
        for (int j = 0; j < 4; j++) {
            redS[ty * 68 + tx * 4 + j] = lsum[j];
            redQ[ty * 68 + tx * 4 + j] = lsq[j];
        }
        __syncthreads();
        for (int o = 8; o > 0; o >>= 1) {
            if (ty < o) {
#pragma unroll
                for (int j = 0; j < 4; j++) {
                    redS[ty * 68 + tx * 4 + j] += redS[(ty + o) * 68 + tx * 4 + j];
                    redQ[ty * 68 + tx * 4 + j] += redQ[(ty + o) * 68 + tx * 4 + j];
                }
            }
            __syncthreads();
        }
        if (ty == 0) {
#pragma unroll
            for (int j = 0; j < 4; j++) {
                atomicAdd(&g_bnsum[tx * 4 + j], redS[tx * 4 + j]);
                atomicAdd(&g_bnsq[tx * 4 + j],  redQ[tx * 4 + j]);
            }
        }
    }
}

// ---------------- batch norm ----------------------------------------------------
__global__ void k_bnfin(const float* __restrict__ gamma, const float* __restrict__ beta) {
    int j = threadIdx.x;
    if (j >= 64) return;
    float mu  = g_bnsum[j] / (float)NN;
    float var = g_bnsq[j] / (float)NN - mu * mu;
    float sc  = gamma[j] * rsqrtf(var + 1e-5f);
    g_bnscale[j] = sc;
    g_bnshift[j] = beta[j] - mu * sc;
}

// ---------------- launch --------------------------------------------------------
extern "C" void kernel_launch(void* const* d_in, const int* in_sizes, int n_in,
                              void* d_out, int out_size) {
    const float* x       = (const float*)d_in[0];
    const float* embed_W = (const float*)d_in[1];
    const float* embed_b = (const float*)d_in[2];
    const float* pre_W1  = (const float*)d_in[3];
    const float* pre_b1  = (const float*)d_in[4];
    const float* post_W1 = (const float*)d_in[5];
    const float* post_b1 = (const float*)d_in[6];
    const float* lin_W1  = (const float*)d_in[7];
    const float* lin_b1  = (const float*)d_in[8];
    const float* bn_g    = (const float*)d_in[9];
    const float* bn_b    = (const float*)d_in[10];
    const float* pre_W2  = (const float*)d_in[11];
    const float* pre_b2  = (const float*)d_in[12];
    const float* post_W2 = (const float*)d_in[13];
    const float* post_b2 = (const float*)d_in[14];
    const float* lin_W2  = (const float*)d_in[15];
    const float* lin_b2  = (const float*)d_in[16];
    const int*   src     = (const int*)d_in[17];
    const int*   dst     = (const int*)d_in[18];
    float* out = (float*)d_out;

    const int GN256 = (NN + 255) / 256;
    const int GE256 = NE / 256;
    const int GT64  = (NN + 63) / 64;      // 782

    // graph structure (shared by both layers)
    k_init<<<GN256, 256>>>();
    k_degree<<<GE256, 256>>>(dst);
    k_logsum<<<GN256, 256>>>();
    k_scales<<<GN256, 256>>>();
    k_scan<<<1, 1024>>>();
    k_scatter<<<GE256, 256>>>(src, dst);

    // embed + weight packing
    k_embed<<<GT64, 256>>>(x, embed_W, embed_b);
    k_preB2both<<<128, 256>>>(pre_W1, pre_W2);

    // ---- layer 1 ----
    k_hds<<<GT64, 256>>>(0);
    k_agg<<<NN / 2, 256>>>(pre_b1);
    k_postlin<<<GT64, 256>>>(post_W1, post_b1, lin_W1, lin_b1, nullptr); // + BN stats

    k_bnfin<<<1, 64>>>(bn_g, bn_b);

    // ---- layer 2 (k_hds applies BN+ReLU inline) ----
    k_hds<<<GT64, 256>>>(1);
    k_agg<<<NN / 2, 256>>>(pre_b2);
    k_postlin<<<GT64, 256>>>(post_W2, post_b2, lin_W2, lin_b2, out);
}

// round 10
// speedup vs baseline: 1.2826x; 1.0639x over previous
#include <cuda_runtime.h>
#include <math.h>

#define NN 50000
#define NE 800000
#define IND 128

// ---------------- scratch ------------------------------------------------------
__device__ float g_hA[NN * 64];        // layer input (embed out / post-BN)
__device__ float g_hB[NN * 64];        // layer1 output (pre-BN)
__device__ float g_Hd[NN * 128];       // h @ preW_top  (dst half)
__device__ float g_Hs[NN * 128];       // h @ preW_bot  (src half) — 25.6MB, L2-resident
__device__ float g_agg[NN * 512];      // per node: [t][stat(mean,min,max,std)][f]
__device__ int   g_deg[NN];
__device__ float g_invc[NN];
__device__ float g_s1[NN];
__device__ float g_s2[NN];
__device__ int   g_rowptr[NN + 1];
__device__ int   g_cursor[NN];
__device__ int   g_csrc[NE];
__device__ float g_preB2a[64 * 256];   // layer1 packed preW  [k][c]
__device__ float g_preB2b[64 * 256];   // layer2 packed preW  [k][c]
__device__ float g_sumlog;
__device__ float g_bnsum[64];
__device__ float g_bnsq[64];
__device__ float g_bnscale[64];
__device__ float g_bnshift[64];

// ---------------- setup --------------------------------------------------------
__global__ void k_init() {
    int i = blockIdx.x * blockDim.x + threadIdx.x;
    if (i < NN) { g_deg[i] = 0; g_cursor[i] = 0; }
    if (i == 0) g_sumlog = 0.f;
    if (i < 64) { g_bnsum[i] = 0.f; g_bnsq[i] = 0.f; }
}

__global__ void k_degree(const int* __restrict__ dst) {
    int e = blockIdx.x * blockDim.x + threadIdx.x;
    if (e < NE) atomicAdd(&g_deg[dst[e]], 1);
}

__global__ void k_logsum() {
    __shared__ float s[256];
    int i = blockIdx.x * 256 + threadIdx.x;
    float v = 0.f;
    if (i < NN) v = logf((float)g_deg[i] + 1.f);
    s[threadIdx.x] = v; __syncthreads();
    for (int o = 128; o > 0; o >>= 1) {
        if (threadIdx.x < o) s[threadIdx.x] += s[threadIdx.x + o];
        __syncthreads();
    }
    if (threadIdx.x == 0) atomicAdd(&g_sumlog, s[0]);
}

__global__ void k_scales() {
    int i = blockIdx.x * blockDim.x + threadIdx.x;
    if (i >= NN) return;
    float avg = g_sumlog / (float)NN;
    float dc  = fmaxf((float)g_deg[i], 1.f);
    g_invc[i] = 1.f / dc;
    float ld  = logf(dc + 1.f);
    g_s1[i] = ld / avg;
    g_s2[i] = avg / ld;
}

__global__ void k_scan() {
    __shared__ int ssum[1024];
    const int CH = (NN + 1023) / 1024;
    int t  = threadIdx.x;
    int lo = t * CH, hi = min(lo + CH, NN);
    int s = 0;
    for (int i = lo; i < hi; i++) s += g_deg[i];
    ssum[t] = s; __syncthreads();
    for (int o = 1; o < 1024; o <<= 1) {
        int v = (t >= o) ? ssum[t - o] : 0;
        __syncthreads();
        ssum[t] += v;
        __syncthreads();
    }
    int run = (t == 0) ? 0 : ssum[t - 1];
    for (int i = lo; i < hi; i++) { g_rowptr[i] = run; run += g_deg[i]; }
    if (t == 1023) g_rowptr[NN] = ssum[1023];
}

__global__ void k_scatter(const int* __restrict__ src, const int* __restrict__ dst) {
    int e = blockIdx.x * blockDim.x + threadIdx.x;
    if (e >= NE) return;
    int d = dst[e];
    int pos = g_rowptr[d] + atomicAdd(&g_cursor[d], 1);
    g_csrc[pos] = src[e];
}

// pack both layers' preW (T,128,64) into [64][256]: col c: half=c>>7, j=c&127
__global__ void k_preB2both(const float* __restrict__ preW1,
                            const float* __restrict__ preW2) {
    int i = blockIdx.x * blockDim.x + threadIdx.x;
    if (i >= 2 * 64 * 256) return;
    int which = i >> 14;               // 0: layer1, 1: layer2
    int u = i & 16383;
    int k = u >> 8, c = u & 255;
    int half = c >> 7, j = c & 127;
    int t = j >> 6, f = j & 63;
    const float* w = which ? preW2 : preW1;
    float* o = which ? g_preB2b : g_preB2a;
    o[u] = w[t * 8192 + (half * 64 + k) * 64 + f];
}

// ---------------- embed GEMM: h = x @ W + b  (K=128, N=64) ----------------------
__global__ __launch_bounds__(256) void k_embed(const float* __restrict__ x,
                                               const float* __restrict__ W,
                                               const float* __restrict__ b) {
    __shared__ float Xs[128][64];
    __shared__ float Ws[128][64];
    int t  = threadIdx.x;
    int n0 = blockIdx.x * 64;

    for (int i = t; i < 2048; i += 256)
        ((float4*)Ws)[i] = ((const float4*)W)[i];

    int row = t & 63, kq = t >> 6;
    int gr = n0 + row;
#pragma unroll
    for (int j = 0; j < 8; j++) {
        int k = kq * 32 + j * 4;
        float4 v = make_float4(0.f, 0.f, 0.f, 0.f);
        if (gr < NN) v = *(const float4*)(x + (size_t)gr * IND + k);
        Xs[k][row] = v.x; Xs[k + 1][row] = v.y; Xs[k + 2][row] = v.z; Xs[k + 3][row] = v.w;
    }
    __syncthreads();

    int tx = t & 15, ty = t >> 4;
    float acc[4][4];
#pragma unroll
    for (int i = 0; i < 4; i++)
#pragma unroll
        for (int j = 0; j < 4; j++) acc[i][j] = 0.f;

#pragma unroll 8
    for (int k = 0; k < 128; k++) {
        float4 a  = *(const float4*)&Xs[k][ty * 4];
        float4 b4 = *(const float4*)&Ws[k][tx * 4];
        float ar[4] = {a.x, a.y, a.z, a.w};
        float br[4] = {b4.x, b4.y, b4.z, b4.w};
#pragma unroll
        for (int i = 0; i < 4; i++)
#pragma unroll
            for (int j = 0; j < 4; j++) acc[i][j] = fmaf(ar[i], br[j], acc[i][j]);
    }

    float4 bias = *(const float4*)(b + tx * 4);
#pragma unroll
    for (int i = 0; i < 4; i++) {
        int gn = n0 + ty * 4 + i;
        if (gn < NN) {
            float4 o = make_float4(acc[i][0] + bias.x, acc[i][1] + bias.y,
                                   acc[i][2] + bias.z, acc[i][3] + bias.w);
            *(float4*)(g_hA + (size_t)gn * 64 + tx * 4) = o;
        }
    }
}

// ---------------- Hd/Hs GEMM: [Hd|Hs] = h @ preB2  (K=64, N=256) ----------------
// layer==1: applies BN (scale/shift) + ReLU to g_hB during the Xs load and
// writes the activated values back to g_hA (replaces the separate bnapply pass).
__global__ __launch_bounds__(256) void k_hds(int layer) {
    __shared__ float Xs[64][64];   // [k][node]
    __shared__ float Bs[64][64];   // [k][c]
    int t  = threadIdx.x;
    int n0 = blockIdx.x * 64;
    const float* preB = layer ? g_preB2b : g_preB2a;

    int node = t & 63, kq = t >> 6;
    int gr = n0 + node;
#pragma unroll
    for (int j = 0; j < 4; j++) {
        int k = kq * 16 + j * 4;
        float4 v = make_float4(0.f, 0.f, 0.f, 0.f);
        if (gr < NN) {
            if (layer == 0) {
                v = *(const float4*)(g_hA + (size_t)gr * 64 + k);
            } else {
                float4 hv = *(const float4*)(g_hB + (size_t)gr * 64 + k);
                v.x = fmaxf(hv.x * g_bnscale[k]     + g_bnshift[k],     0.f);
                v.y = fmaxf(hv.y * g_bnscale[k + 1] + g_bnshift[k + 1], 0.f);
                v.z = fmaxf(hv.z * g_bnscale[k + 2] + g_bnshift[k + 2], 0.f);
                v.w = fmaxf(hv.w * g_bnscale[k + 3] + g_bnshift[k + 3], 0.f);
                *(float4*)(g_hA + (size_t)gr * 64 + k) = v;   // layer-2 h input
            }
        }
        Xs[k][node] = v.x; Xs[k + 1][node] = v.y; Xs[k + 2][node] = v.z; Xs[k + 3][node] = v.w;
    }

    int tx = t & 15, ty = t >> 4;

    for (int cg = 0; cg < 4; cg++) {
        __syncthreads();   // Xs ready (cg=0) / previous Bs fully consumed
#pragma unroll
        for (int i = 0; i < 4; i++) {
            int u = t + 256 * i;
            int k = u >> 4, cq = u & 15;
            *(float4*)&Bs[k][cq * 4] = *(const float4*)(preB + k * 256 + cg * 64 + cq * 4);
        }
        __syncthreads();

        float acc[4][4];
#pragma unroll
        for (int i = 0; i < 4; i++)
#pragma unroll
            for (int j = 0; j < 4; j++) acc[i][j] = 0.f;

#pragma unroll 8
        for (int k = 0; k < 64; k++) {
            float4 a  = *(const float4*)&Xs[k][ty * 4];
            float4 b4 = *(const float4*)&Bs[k][tx * 4];
            float ar[4] = {a.x, a.y, a.z, a.w};
            float br[4] = {b4.x, b4.y, b4.z, b4.w};
#pragma unroll
            for (int i = 0; i < 4; i++)
#pragma unroll
                for (int j = 0; j < 4; j++) acc[i][j] = fmaf(ar[i], br[j], acc[i][j]);
        }

        int c0 = cg * 64 + tx * 4;
#pragma unroll
        for (int i = 0; i < 4; i++) {
            int gn = n0 + ty * 4 + i;
            if (gn < NN) {
                float4 o = make_float4(acc[i][0], acc[i][1], acc[i][2], acc[i][3]);
                if (c0 < 128) *(float4*)(g_Hd + (size_t)gn * 128 + c0) = o;
                else          *(float4*)(g_Hs + (size_t)gn * 128 + (c0 - 128)) = o;
            }
        }
    }
}

// ---------------- fused gather+aggregate (2 nodes per block) --------------------
__global__ __launch_bounds__(256) void k_agg(const float* __restrict__ preb) {
    int n = blockIdx.x * 2 + (threadIdx.x >> 7);
    int f = threadIdx.x & 127;     // 0..127
    int lo = g_rowptr[n], hi = g_rowptr[n + 1];
    float sum = 0.f, sq = 0.f;
    float mn = INFINITY, mx = -INFINITY;
    int p = lo;
    for (; p + 4 <= hi; p += 4) {
        int i0 = g_csrc[p], i1 = g_csrc[p + 1], i2 = g_csrc[p + 2], i3 = g_csrc[p + 3];
        float v0 = g_Hs[(size_t)i0 * 128 + f];
        float v1 = g_Hs[(size_t)i1 * 128 + f];
        float v2 = g_Hs[(size_t)i2 * 128 + f];
        float v3 = g_Hs[(size_t)i3 * 128 + f];
        sum += (v0 + v1) + (v2 + v3);
        sq  = fmaf(v0, v0, fmaf(v1, v1, fmaf(v2, v2, fmaf(v3, v3, sq))));
        mn = fminf(mn, fminf(fminf(v0, v1), fminf(v2, v3)));
        mx = fmaxf(mx, fmaxf(fmaxf(v0, v1), fmaxf(v2, v3)));
    }
    for (; p < hi; p++) {
        float v = g_Hs[(size_t)g_csrc[p] * 128 + f];
        sum += v; sq = fmaf(v, v, sq);
        mn = fminf(mn, v); mx = fmaxf(mx, v);
    }
    float c = g_Hd[(size_t)n * 128 + f] + preb[f];
    int deg = hi - lo;
    float mean, mnO, mxO, sd;
    if (deg > 0) {
        float invc = g_invc[n];
        float ms  = sum * invc;
        float var = sq * invc - ms * ms;
        mean = c + ms; mnO = c + mn; mxO = c + mx;
        sd = sqrtf(fmaxf(var, 0.f) + 1e-5f);
    } else {
        mean = 0.f; mnO = 0.f; mxO = 0.f; sd = sqrtf(1e-5f);
    }
    int tt = f >> 6, ff = f & 63;
    size_t base = (size_t)n * 512 + tt * 256 + ff;
    g_agg[base]       = mean;
    g_agg[base + 64]  = mnO;
    g_agg[base + 128] = mxO;
    g_agg[base + 192] = sd;
}

// ---------------- fused post+lin GEMM -------------------------------------------
// Stage 1: P[64 nodes][64 cols] over K=832 (13 chunks of 64), vectorized reads:
//   kk steps by 4; 4x LDS.128 row-reads + 4x LDS.128 W-reads per 64 FMA (89% issue).
// Stage 2: out = P @ linW + linb in-block (K=64, same pattern).
// Layer 1 (outp==nullptr): writes g_hB and accumulates BN column stats.
#define TSTRIDE 4360   // tower stride in floats (4360 % 32 = 8 -> disjoint banks)
__global__ __launch_bounds__(256) void k_postlin(const float* __restrict__ postW,
                                                 const float* __restrict__ postb,
                                                 const float* __restrict__ linW,
                                                 const float* __restrict__ linb,
                                                 float* __restrict__ outp) {
    __shared__ float A13[2 * TSTRIDE]; // [tower][node(64)][k(68 pad)] — 34880 B
    __shared__ float Ws[64][64];       // weights tile — 16384 B
    int t  = threadIdx.x;
    int n0 = blockIdx.x * 64;
    int tx = t & 15, ty = t >> 4;
    int tc = tx >> 3;                  // tower for this thread's columns
    int abase = tc * TSTRIDE + ty * 4 * 68;   // this thread's 4 node rows

    float acc[4][4];
#pragma unroll
    for (int i = 0; i < 4; i++)
#pragma unroll
        for (int j = 0; j < 4; j++) acc[i][j] = 0.f;

    for (int ci = 0; ci < 13; ci++) {
        int kc = ci * 64;
        float4 va[8];
#pragma unroll
        for (int i = 0; i < 8; i++) {
            int u = t + 256 * i;
            int tw = u >> 10, node = (u >> 4) & 63, kq = u & 15;
            int gn = n0 + node;
            float4 v = make_float4(0.f, 0.f, 0.f, 0.f);
            if (gn < NN) {
                if (ci == 0) {
                    v = *(const float4*)(g_hA + (size_t)gn * 64 + kq * 4);
                } else {
                    int k = kc + kq * 4;
                    int j; float s = 1.f;
                    if (ci < 5)      { j = k - 64; }
                    else if (ci < 9) { j = k - 320; s = g_s1[gn]; }
                    else             { j = k - 576; s = g_s2[gn]; }
                    v = *(const float4*)(g_agg + (size_t)gn * 512 + tw * 256 + j);
                    v.x *= s; v.y *= s; v.z *= s; v.w *= s;
                }
            }
            va[i] = v;
        }
        float4 vb[4];
#pragma unroll
        for (int i = 0; i < 4; i++) {
            int u = t + 256 * i;
            int kk = u >> 4, cq = u & 15;
            int tw = cq >> 3, g = (cq * 4) & 31;
            vb[i] = *(const float4*)(postW + tw * 26624 + (kc + kk) * 32 + g);
        }
        __syncthreads();
#pragma unroll
        for (int i = 0; i < 8; i++) {
            int u = t + 256 * i;
            int tw = u >> 10, node = (u >> 4) & 63, kq = u & 15;
            *(float4*)&A13[tw * TSTRIDE + node * 68 + kq * 4] = va[i];
        }
#pragma unroll
        for (int i = 0; i < 4; i++) ((float4*)Ws)[t + 256 * i] = vb[i];
        __syncthreads();

#pragma unroll
        for (int kk = 0; kk < 64; kk += 4) {
            float4 ar4[4];
#pragma unroll
            for (int i = 0; i < 4; i++)
                ar4[i] = *(const float4*)&A13[abase + i * 68 + kk];
#pragma unroll
            for (int d = 0; d < 4; d++) {
                float4 b4 = *(const float4*)&Ws[kk + d][tx * 4];
                float br[4] = {b4.x, b4.y, b4.z, b4.w};
#pragma unroll
                for (int i = 0; i < 4; i++) {
                    float av = (&ar4[i].x)[d];
#pragma unroll
                    for (int j = 0; j < 4; j++) acc[i][j] = fmaf(av, br[j], acc[i][j]);
                }
            }
        }
        __syncthreads();
    }

    // -------- stage 2: P-tile -> smem (tower-0 area), multiply by linW --------
    float4 pbias = *(const float4*)(postb + tx * 4);
#pragma unroll
    for (int i = 0; i < 4; i++) {
        int r = (ty * 4 + i) * 68;
        A13[r + tx * 4 + 0] = acc[i][0] + pbias.x;
        A13[r + tx * 4 + 1] = acc[i][1] + pbias.y;
        A13[r + tx * 4 + 2] = acc[i][2] + pbias.z;
        A13[r + tx * 4 + 3] = acc[i][3] + pbias.w;
    }
#pragma unroll
    for (int i = 0; i < 4; i++)
        ((float4*)Ws)[t + 256 * i] = ((const float4*)linW)[t + 256 * i];
    __syncthreads();

    float acc2[4][4];
#pragma unroll
    for (int i = 0; i < 4; i++)
#pragma unroll
        for (int j = 0; j < 4; j++) acc2[i][j] = 0.f;

    int a2base = ty * 4 * 68;
#pragma unroll
    for (int kk = 0; kk < 64; kk += 4) {
        float4 ar4[4];
#pragma unroll
        for (int i = 0; i < 4; i++)
            ar4[i] = *(const float4*)&A13[a2base + i * 68 + kk];
#pragma unroll
        for (int d = 0; d < 4; d++) {
            float4 b4 = *(const float4*)&Ws[kk + d][tx * 4];
            float br[4] = {b4.x, b4.y, b4.z, b4.w};
#pragma unroll
            for (int i = 0; i < 4; i++) {
                float av = (&ar4[i].x)[d];
#pragma unroll
                for (int j = 0; j < 4; j++) acc2[i][j] = fmaf(av, br[j], acc2[i][j]);
            }
        }
    }

    float* target = outp ? outp : g_hB;
    float4 lbias = *(const float4*)(linb + tx * 4);
    float lsum[4] = {0.f, 0.f, 0.f, 0.f};
    float lsq[4]  = {0.f, 0.f, 0.f, 0.f};
#pragma unroll
    for (int i = 0; i < 4; i++) {
        int gn = n0 + ty * 4 + i;
        if (gn < NN) {
            float o0 = acc2[i][0] + lbias.x, o1 = acc2[i][1] + lbias.y;
            float o2 = acc2[i][2] + lbias.z, o3 = acc2[i][3] + lbias.w;
            *(float4*)(target + (size_t)gn * 64 + tx * 4) = make_float4(o0, o1, o2, o3);
            lsum[0] += o0; lsum[1] += o1; lsum[2] += o2; lsum[3] += o3;
            lsq[0] = fmaf(o0, o0, lsq[0]); lsq[1] = fmaf(o1, o1, lsq[1]);
            lsq[2] = fmaf(o2, o2, lsq[2]); lsq[3] = fmaf(o3, o3, lsq[3]);
        }
    }

    if (!outp) {   // fused BN stats (layer 1)
        __syncthreads();
        float* redS = &A13[TSTRIDE];   // tower-1 area, no longer needed
        float* redQ = &Ws[0][0];
#pragma unroll
        for (int j = 0; j < 4; j++) {
            redS[ty * 68 + tx * 4 + j] = lsum[j];
            redQ[ty * 68 + tx * 4 + j] = lsq[j];
        }
        __syncthreads();
        for (int o = 8; o > 0; o >>= 1) {
            if (ty < o) {
#pragma unroll
                for (int j = 0; j < 4; j++) {
                    redS[ty * 68 + tx * 4 + j] += redS[(ty + o) * 68 + tx * 4 + j];
                    redQ[ty * 68 + tx * 4 + j] += redQ[(ty + o) * 68 + tx * 4 + j];
                }
            }
            __syncthreads();
        }
        if (ty == 0) {
#pragma unroll
            for (int j = 0; j < 4; j++) {
                atomicAdd(&g_bnsum[tx * 4 + j], redS[tx * 4 + j]);
                atomicAdd(&g_bnsq[tx * 4 + j],  redQ[tx * 4 + j]);
            }
        }
    }
}

// ---------------- batch norm ----------------------------------------------------
__global__ void k_bnfin(const float* __restrict__ gamma, const float* __restrict__ beta) {
    int j = threadIdx.x;
    if (j >= 64) return;
    float mu  = g_bnsum[j] / (float)NN;
    float var = g_bnsq[j] / (float)NN - mu * mu;
    float sc  = gamma[j] * rsqrtf(var + 1e-5f);
    g_bnscale[j] = sc;
    g_bnshift[j] = beta[j] - mu * sc;
}

// ---------------- launch --------------------------------------------------------
extern "C" void kernel_launch(void* const* d_in, const int* in_sizes, int n_in,
                              void* d_out, int out_size) {
    const float* x       = (const float*)d_in[0];
    const float* embed_W = (const float*)d_in[1];
    const float* embed_b = (const float*)d_in[2];
    const float* pre_W1  = (const float*)d_in[3];
    const float* pre_b1  = (const float*)d_in[4];
    const float* post_W1 = (const float*)d_in[5];
    const float* post_b1 = (const float*)d_in[6];
    const float* lin_W1  = (const float*)d_in[7];
    const float* lin_b1  = (const float*)d_in[8];
    const float* bn_g    = (const float*)d_in[9];
    const float* bn_b    = (const float*)d_in[10];
    const float* pre_W2  = (const float*)d_in[11];
    const float* pre_b2  = (const float*)d_in[12];
    const float* post_W2 = (const float*)d_in[13];
    const float* post_b2 = (const float*)d_in[14];
    const float* lin_W2  = (const float*)d_in[15];
    const float* lin_b2  = (const float*)d_in[16];
    const int*   src     = (const int*)d_in[17];
    const int*   dst     = (const int*)d_in[18];
    float* out = (float*)d_out;

    const int GN256 = (NN + 255) / 256;
    const int GE256 = NE / 256;
    const int GT64  = (NN + 63) / 64;      // 782

    // graph structure (shared by both layers)
    k_init<<<GN256, 256>>>();
    k_degree<<<GE256, 256>>>(dst);
    k_logsum<<<GN256, 256>>>();
    k_scales<<<GN256, 256>>>();
    k_scan<<<1, 1024>>>();
    k_scatter<<<GE256, 256>>>(src, dst);

    // embed + weight packing
    k_embed<<<GT64, 256>>>(x, embed_W, embed_b);
    k_preB2both<<<128, 256>>>(pre_W1, pre_W2);

    // ---- layer 1 ----
    k_hds<<<GT64, 256>>>(0);
    k_agg<<<NN / 2, 256>>>(pre_b1);
    k_postlin<<<GT64, 256>>>(post_W1, post_b1, lin_W1, lin_b1, nullptr); // + BN stats

    k_bnfin<<<1, 64>>>(bn_g, bn_b);

    // ---- layer 2 (k_hds applies BN+ReLU inline) ----
    k_hds<<<GT64, 256>>>(1);
    k_agg<<<NN / 2, 256>>>(pre_b2);
    k_postlin<<<GT64, 256>>>(post_W2, post_b2, lin_W2, lin_b2, out);
}